// round 9
// baseline (speedup 1.0000x reference)
#include <cuda_runtime.h>
#include <cstdint>

#define BATCH 512
#define NCTX  1000
#define DCTX  128
#define NH    8
#define HID   128
#define TPB   128
#define NSPLIT 4
#define RPB   250      // rows per block (pass kernels)

typedef unsigned long long ull;

// ---- global scratch (static; no allocations) ----
__device__ float g_part[BATCH][NSPLIT][1032];  // [0..1023]=c partial, [1024..1031]=l partial
__device__ float g_z[BATCH][128];
__device__ float g_u[BATCH][1024];

__device__ __forceinline__ ull f2pack(float lo, float hi) {
    ull r; asm("mov.b64 %0, {%1,%2};" : "=l"(r) : "f"(lo), "f"(hi)); return r;
}
__device__ __forceinline__ void f2unpack(ull v, float &lo, float &hi) {
    asm("mov.b64 {%0,%1}, %2;" : "=f"(lo), "=f"(hi) : "l"(v));
}
__device__ __forceinline__ ull ffma2(ull a, ull b, ull c) {
    ull d; asm("fma.rn.f32x2 %0, %1, %2, %3;" : "=l"(d) : "l"(a), "l"(b), "l"(c)); return d;
}

// split-butterfly: p[8] partials/lane -> full 32-lane sum of index bitrev3(lane&7),
// replicated over the 4 lanes sharing lane&7. 9 SHFL.
__device__ __forceinline__ float split_butterfly8(const float* p, int lane) {
    bool h1 = (lane & 1) != 0;
    float k0 = h1 ? p[4] : p[0], k1 = h1 ? p[5] : p[1];
    float k2 = h1 ? p[6] : p[2], k3 = h1 ? p[7] : p[3];
    float s0 = h1 ? p[0] : p[4], s1 = h1 ? p[1] : p[5];
    float s2 = h1 ? p[2] : p[6], s3 = h1 ? p[3] : p[7];
    k0 += __shfl_xor_sync(0xffffffffu, s0, 1);
    k1 += __shfl_xor_sync(0xffffffffu, s1, 1);
    k2 += __shfl_xor_sync(0xffffffffu, s2, 1);
    k3 += __shfl_xor_sync(0xffffffffu, s3, 1);
    bool h2 = (lane & 2) != 0;
    float t0 = h2 ? k2 : k0, t1 = h2 ? k3 : k1;
    float u0 = h2 ? k0 : k2, u1 = h2 ? k1 : k3;
    t0 += __shfl_xor_sync(0xffffffffu, u0, 2);
    t1 += __shfl_xor_sync(0xffffffffu, u1, 2);
    bool h4 = (lane & 4) != 0;
    float v = h4 ? t1 : t0;
    float w = h4 ? t0 : t1;
    v += __shfl_xor_sync(0xffffffffu, w, 4);
    v += __shfl_xor_sync(0xffffffffu, v, 8);
    v += __shfl_xor_sync(0xffffffffu, v, 16);
    return v;
}
__device__ __forceinline__ int bitrev3(int l) {
    return ((l & 1) << 2) | (l & 2) | ((l >> 2) & 1);
}

// ============================ K1: pass-1 partials ============================
__global__ void __launch_bounds__(TPB, 4)
k1_attn_partial(const float* __restrict__ state_t,
                const float* __restrict__ context,
                const int*   __restrict__ mask,
                const float* __restrict__ Wq,
                const float* __restrict__ Wk_mha)
{
    __shared__ float sqkT[1024];
    __shared__ float sscr[4096];
    __shared__ float ssq[128];
    __shared__ float sstate[384];
    __shared__ float sswl[32];
    __shared__ int   smask[RPB];

    const int s = blockIdx.x, b = blockIdx.y;
    const int t = threadIdx.x;
    const int w = t >> 5, lane = t & 31;
    const int blkbase = s * RPB;

    for (int i = t; i < RPB; i += TPB) smask[i] = mask[(size_t)b * NCTX + blkbase + i];
    for (int i = t; i < 384; i += TPB) sstate[i] = state_t[(size_t)b * 384 + i];
    __syncthreads();

    // q[o] = state . Wq[:,o]
    {
        float a0 = 0.f, a1 = 0.f, a2 = 0.f, a3 = 0.f;
        const float* wq = Wq + t;
#pragma unroll 4
        for (int i = 0; i < 384; i += 4) {
            a0 = fmaf(sstate[i],     wq[(size_t)i * HID], a0);
            a1 = fmaf(sstate[i + 1], wq[(size_t)(i + 1) * HID], a1);
            a2 = fmaf(sstate[i + 2], wq[(size_t)(i + 2) * HID], a2);
            a3 = fmaf(sstate[i + 3], wq[(size_t)(i + 3) * HID], a3);
        }
        ssq[t] = (a0 + a1) + (a2 + a3);
    }
    __syncthreads();

    // qkT[d][h] = 0.25 * sum_j Wk_mha[d][16h+j] * q[16h+j]
    {
        int h = t & 7, d0 = t >> 3;
#pragma unroll
        for (int dd = 0; dd < 8; ++dd) {
            int d = d0 + dd * 16;
            float p = 0.f;
#pragma unroll
            for (int j = 0; j < 16; ++j)
                p = fmaf(Wk_mha[d * HID + h * 16 + j], ssq[h * 16 + j], p);
            sqkT[d * 8 + h] = 0.25f * p;
        }
    }
    __syncthreads();

    ull qkp[4][4];
#pragma unroll
    for (int dd = 0; dd < 4; ++dd)
#pragma unroll
        for (int hp = 0; hp < 4; ++hp)
            qkp[dd][hp] = *(const ull*)(sqkT + (lane * 4 + dd) * 8 + hp * 2);
    const int hsel = bitrev3(lane & 7);

    const float* ctxb = context + ((size_t)b * NCTX + blkbase) * DCTX;
    const int lbase = w * 63;                       // local row base within block
    const int nr = (w < 3) ? 63 : (RPB - 3 * 63);   // 63,63,63,61

    ull acc[NH][2];
#pragma unroll
    for (int hh = 0; hh < NH; ++hh) { acc[hh][0] = 0ull; acc[hh][1] = 0ull; }
    float lrun = 0.f;

    for (int i0 = 0; i0 < 63; i0 += 4) {
        float4 cv[4];
#pragma unroll
        for (int r = 0; r < 4; ++r) {
            int rr = i0 + r;
            int safe = (rr < nr) ? rr : 0;
            cv[r] = *(const float4*)(ctxb + (size_t)(lbase + safe) * DCTX + lane * 4);
        }
#pragma unroll
        for (int r = 0; r < 4; ++r) {
            int rr = i0 + r;
            ull cc0 = f2pack(cv[r].x, cv[r].x), cc1 = f2pack(cv[r].y, cv[r].y);
            ull cc2 = f2pack(cv[r].z, cv[r].z), cc3 = f2pack(cv[r].w, cv[r].w);
            ull p01 = 0ull, p23 = 0ull, p45 = 0ull, p67 = 0ull;
            p01 = ffma2(cc0, qkp[0][0], p01); p23 = ffma2(cc0, qkp[0][1], p23);
            p45 = ffma2(cc0, qkp[0][2], p45); p67 = ffma2(cc0, qkp[0][3], p67);
            p01 = ffma2(cc1, qkp[1][0], p01); p23 = ffma2(cc1, qkp[1][1], p23);
            p45 = ffma2(cc1, qkp[1][2], p45); p67 = ffma2(cc1, qkp[1][3], p67);
            p01 = ffma2(cc2, qkp[2][0], p01); p23 = ffma2(cc2, qkp[2][1], p23);
            p45 = ffma2(cc2, qkp[2][2], p45); p67 = ffma2(cc2, qkp[2][3], p67);
            p01 = ffma2(cc3, qkp[3][0], p01); p23 = ffma2(cc3, qkp[3][1], p23);
            p45 = ffma2(cc3, qkp[3][2], p45); p67 = ffma2(cc3, qkp[3][3], p67);

            float pv[8];
            f2unpack(p01, pv[0], pv[1]); f2unpack(p23, pv[2], pv[3]);
            f2unpack(p45, pv[4], pv[5]); f2unpack(p67, pv[6], pv[7]);
            float compv = split_butterfly8(pv, lane);

            bool dead = (rr >= nr) || (smask[lbase + rr] != 0);
            float e = dead ? 0.f : __expf(compv);
            if (lane < 8) lrun += e;

            float eh0 = __shfl_sync(0xffffffffu, e, 0);
            float eh1 = __shfl_sync(0xffffffffu, e, 4);
            float eh2 = __shfl_sync(0xffffffffu, e, 2);
            float eh3 = __shfl_sync(0xffffffffu, e, 6);
            float eh4 = __shfl_sync(0xffffffffu, e, 1);
            float eh5 = __shfl_sync(0xffffffffu, e, 5);
            float eh6 = __shfl_sync(0xffffffffu, e, 3);
            float eh7 = __shfl_sync(0xffffffffu, e, 7);

            ull c01 = f2pack(cv[r].x, cv[r].y), c23 = f2pack(cv[r].z, cv[r].w);
            ull e2;
            e2 = f2pack(eh0, eh0); acc[0][0] = ffma2(c01, e2, acc[0][0]); acc[0][1] = ffma2(c23, e2, acc[0][1]);
            e2 = f2pack(eh1, eh1); acc[1][0] = ffma2(c01, e2, acc[1][0]); acc[1][1] = ffma2(c23, e2, acc[1][1]);
            e2 = f2pack(eh2, eh2); acc[2][0] = ffma2(c01, e2, acc[2][0]); acc[2][1] = ffma2(c23, e2, acc[2][1]);
            e2 = f2pack(eh3, eh3); acc[3][0] = ffma2(c01, e2, acc[3][0]); acc[3][1] = ffma2(c23, e2, acc[3][1]);
            e2 = f2pack(eh4, eh4); acc[4][0] = ffma2(c01, e2, acc[4][0]); acc[4][1] = ffma2(c23, e2, acc[4][1]);
            e2 = f2pack(eh5, eh5); acc[5][0] = ffma2(c01, e2, acc[5][0]); acc[5][1] = ffma2(c23, e2, acc[5][1]);
            e2 = f2pack(eh6, eh6); acc[6][0] = ffma2(c01, e2, acc[6][0]); acc[6][1] = ffma2(c23, e2, acc[6][1]);
            e2 = f2pack(eh7, eh7); acc[7][0] = ffma2(c01, e2, acc[7][0]); acc[7][1] = ffma2(c23, e2, acc[7][1]);
        }
    }

    // block-reduce 4 warps -> global partial slot
    {
        float* scr = sscr + w * 1024;
#pragma unroll
        for (int hh = 0; hh < NH; ++hh) {
            float x0, x1, x2, x3;
            f2unpack(acc[hh][0], x0, x1);
            f2unpack(acc[hh][1], x2, x3);
            *(float4*)(scr + hh * DCTX + lane * 4) = make_float4(x0, x1, x2, x3);
        }
        if (lane < 8) sswl[w * 8 + hsel] = lrun;
    }
    __syncthreads();
#pragma unroll
    for (int jj = 0; jj < 8; ++jj) {
        int idx = t + jj * TPB;
        g_part[b][s][idx] = (sscr[idx] + sscr[1024 + idx]) + (sscr[2048 + idx] + sscr[3072 + idx]);
    }
    if (t < 8)
        g_part[b][s][1024 + t] = (sswl[t] + sswl[8 + t]) + (sswl[16 + t] + sswl[24 + t]);
}

// ============================ K2: combine + project ============================
__global__ void __launch_bounds__(TPB, 8)
k2_project(const float* __restrict__ Wv,
           const float* __restrict__ Wfc,
           const float* __restrict__ Wk)
{
    __shared__ float ssc[1024];
    __shared__ float ssl[8];
    __shared__ float ssx[128];
    __shared__ float ssxf[128];

    const int b = blockIdx.x;
    const int t = threadIdx.x;

#pragma unroll
    for (int jj = 0; jj < 8; ++jj) {
        int idx = t + jj * TPB;
        ssc[idx] = (g_part[b][0][idx] + g_part[b][1][idx])
                 + (g_part[b][2][idx] + g_part[b][3][idx]);
    }
    if (t < 8)
        ssl[t] = (g_part[b][0][1024 + t] + g_part[b][1][1024 + t])
               + (g_part[b][2][1024 + t] + g_part[b][3][1024 + t]);
    __syncthreads();

    // x[o] = (1/l_h) sum_d c[h][d] Wv[d][o]
    {
        int hh = t >> 4;
        const float* c = ssc + hh * DCTX;
        float a0 = 0.f, a1 = 0.f, a2 = 0.f, a3 = 0.f;
#pragma unroll 4
        for (int d = 0; d < DCTX; d += 4) {
            a0 = fmaf(c[d],     Wv[(size_t)d * HID + t], a0);
            a1 = fmaf(c[d + 1], Wv[(size_t)(d + 1) * HID + t], a1);
            a2 = fmaf(c[d + 2], Wv[(size_t)(d + 2) * HID + t], a2);
            a3 = fmaf(c[d + 3], Wv[(size_t)(d + 3) * HID + t], a3);
        }
        ssx[t] = ((a0 + a1) + (a2 + a3)) / ssl[hh];
    }
    __syncthreads();
    // xf = x @ Wfc
    {
        float a0 = 0.f, a1 = 0.f, a2 = 0.f, a3 = 0.f;
#pragma unroll 4
        for (int i = 0; i < HID; i += 4) {
            a0 = fmaf(ssx[i],     Wfc[(size_t)i * HID + t], a0);
            a1 = fmaf(ssx[i + 1], Wfc[(size_t)(i + 1) * HID + t], a1);
            a2 = fmaf(ssx[i + 2], Wfc[(size_t)(i + 2) * HID + t], a2);
            a3 = fmaf(ssx[i + 3], Wfc[(size_t)(i + 3) * HID + t], a3);
        }
        ssxf[t] = (a0 + a1) + (a2 + a3);
    }
    __syncthreads();
    // z[d] = (1/sqrt(HID)) sum_o Wk[d][o] xf[o]
    {
        const float* wk = Wk + (size_t)t * HID;
        float a0 = 0.f, a1 = 0.f, a2 = 0.f, a3 = 0.f;
#pragma unroll 4
        for (int o = 0; o < HID; o += 4) {
            a0 = fmaf(wk[o],     ssxf[o], a0);
            a1 = fmaf(wk[o + 1], ssxf[o + 1], a1);
            a2 = fmaf(wk[o + 2], ssxf[o + 2], a2);
            a3 = fmaf(wk[o + 3], ssxf[o + 3], a3);
        }
        g_z[b][t] = 0.08838834764831845f * ((a0 + a1) + (a2 + a3));
    }
}

// ============================ K3: pointer pass ============================
__global__ void __launch_bounds__(TPB, 8)
k3_pointer(const float* __restrict__ context,
           const int*   __restrict__ mask)
{
    __shared__ int smask[RPB];

    const int s = blockIdx.x, b = blockIdx.y;
    const int t = threadIdx.x;
    const int w = t >> 5, lane = t & 31;
    const int blkbase = s * RPB;
    const float NEG_INF = __int_as_float(0xff800000u);

    for (int i = t; i < RPB; i += TPB) smask[i] = mask[(size_t)b * NCTX + blkbase + i];

    float4 zv = *(const float4*)(&g_z[b][lane * 4]);
    ull z01 = f2pack(zv.x, zv.y), z23 = f2pack(zv.z, zv.w);
    __syncthreads();

    const float* ctxb = context + ((size_t)b * NCTX + blkbase) * DCTX;
    const int lbase = w * 63;
    const int nr = (w < 3) ? 63 : (RPB - 3 * 63);
    const int hsel = bitrev3(lane & 7);

    for (int ib = 0; ib < 8; ++ib) {
        float dr[8];
#pragma unroll
        for (int r = 0; r < 8; ++r) {
            int rr = ib * 8 + r;
            int safe = (rr < nr) ? rr : 0;
            float4 cv = *(const float4*)(ctxb + (size_t)(lbase + safe) * DCTX + lane * 4);
            ull s2 = ffma2(f2pack(cv.z, cv.w), z23, 0ull);
            s2 = ffma2(f2pack(cv.x, cv.y), z01, s2);
            float a0, a1; f2unpack(s2, a0, a1);
            dr[r] = a0 + a1;
        }
        float ud = split_butterfly8(dr, lane);
        if (lane < 8) {
            int rr = ib * 8 + hsel;
            if (rr < nr) {
                float uv = (smask[lbase + rr] != 0) ? NEG_INF : 5.f * tanhf(ud);
                g_u[b][blkbase + lbase + rr] = uv;
            }
        }
    }
}

// ============================ K4: final softmax ============================
__global__ void __launch_bounds__(TPB, 8)
k4_softmax(const int* __restrict__ Tptr, float* __restrict__ out)
{
    __shared__ float sred[8];
    const int b = blockIdx.x;
    const int t = threadIdx.x;
    const int w = t >> 5, lane = t & 31;
    const float NEG_INF = __int_as_float(0xff800000u);

    float uk[8];
    float m = NEG_INF;
#pragma unroll
    for (int k = 0; k < 8; ++k) {
        int idx = t + k * TPB;
        uk[k] = (idx < NCTX) ? g_u[b][idx] : NEG_INF;
        m = fmaxf(m, uk[k]);
    }
    m = fmaxf(m, __shfl_xor_sync(0xffffffffu, m, 16));
    m = fmaxf(m, __shfl_xor_sync(0xffffffffu, m, 8));
    m = fmaxf(m, __shfl_xor_sync(0xffffffffu, m, 4));
    m = fmaxf(m, __shfl_xor_sync(0xffffffffu, m, 2));
    m = fmaxf(m, __shfl_xor_sync(0xffffffffu, m, 1));
    if (lane == 0) sred[w] = m;
    __syncthreads();
    float umax = fmaxf(fmaxf(sred[0], sred[1]), fmaxf(sred[2], sred[3]));

    float invT;
    {
        int iv = Tptr[0];
        float Tv = (iv >= 1 && iv <= 1000000) ? (float)iv : __int_as_float(iv);
        if (!(Tv > 0.f)) Tv = 1.f;
        invT = 1.f / Tv;
    }

    float ssum = 0.f;
#pragma unroll
    for (int k = 0; k < 8; ++k) {
        uk[k] = __expf((uk[k] - umax) * invT);
        ssum += uk[k];
    }
    ssum += __shfl_xor_sync(0xffffffffu, ssum, 16);
    ssum += __shfl_xor_sync(0xffffffffu, ssum, 8);
    ssum += __shfl_xor_sync(0xffffffffu, ssum, 4);
    ssum += __shfl_xor_sync(0xffffffffu, ssum, 2);
    ssum += __shfl_xor_sync(0xffffffffu, ssum, 1);
    if (lane == 0) sred[4 + w] = ssum;
    __syncthreads();
    float inv_sum = 1.f / ((sred[4] + sred[5]) + (sred[6] + sred[7]));

#pragma unroll
    for (int k = 0; k < 8; ++k) {
        int idx = t + k * TPB;
        if (idx < NCTX) out[(size_t)b * NCTX + idx] = uk[k] * inv_sum;
    }
}

extern "C" void kernel_launch(void* const* d_in, const int* in_sizes, int n_in,
                              void* d_out, int out_size)
{
    const float* state_t = (const float*)d_in[0];
    const float* context = (const float*)d_in[1];
    const int*   mask    = (const int*)d_in[2];
    const float* Wq      = (const float*)d_in[3];
    const float* Wk_mha  = (const float*)d_in[4];
    const float* Wv      = (const float*)d_in[5];
    const float* Wfc     = (const float*)d_in[6];
    const float* Wk      = (const float*)d_in[7];
    const int*   Tptr    = (const int*)d_in[8];

    dim3 gridP(NSPLIT, BATCH);
    k1_attn_partial<<<gridP, TPB>>>(state_t, context, mask, Wq, Wk_mha);
    k2_project<<<BATCH, TPB>>>(Wv, Wfc, Wk);
    k3_pointer<<<gridP, TPB>>>(context, mask);
    k4_softmax<<<BATCH, TPB>>>(Tptr, (float*)d_out);
}

// round 10
// speedup vs baseline: 1.4778x; 1.4778x over previous
#include <cuda_runtime.h>
#include <cstdint>

#define BATCH 512
#define NCTX  1000
#define DCTX  128
#define NH    8
#define HID   128
#define TPB   128
#define RPW   256   // rows per warp

typedef unsigned long long ull;

__device__ __forceinline__ ull f2pack(float lo, float hi) {
    ull r; asm("mov.b64 %0, {%1,%2};" : "=l"(r) : "f"(lo), "f"(hi)); return r;
}
__device__ __forceinline__ void f2unpack(ull v, float &lo, float &hi) {
    asm("mov.b64 {%0,%1}, %2;" : "=f"(lo), "=f"(hi) : "l"(v));
}
__device__ __forceinline__ ull ffma2(ull a, ull b, ull c) {
    ull d; asm("fma.rn.f32x2 %0, %1, %2, %3;" : "=l"(d) : "l"(a), "l"(b), "l"(c)); return d;
}

// split-butterfly: p[8] partials/lane -> full 32-lane sum of index bitrev3(lane&7),
// replicated over the 4 lanes sharing lane&7. 9 SHFL.
__device__ __forceinline__ float split_butterfly8(const float* p, int lane) {
    bool h1 = (lane & 1) != 0;
    float k0 = h1 ? p[4] : p[0], k1 = h1 ? p[5] : p[1];
    float k2 = h1 ? p[6] : p[2], k3 = h1 ? p[7] : p[3];
    float s0 = h1 ? p[0] : p[4], s1 = h1 ? p[1] : p[5];
    float s2 = h1 ? p[2] : p[6], s3 = h1 ? p[3] : p[7];
    k0 += __shfl_xor_sync(0xffffffffu, s0, 1);
    k1 += __shfl_xor_sync(0xffffffffu, s1, 1);
    k2 += __shfl_xor_sync(0xffffffffu, s2, 1);
    k3 += __shfl_xor_sync(0xffffffffu, s3, 1);
    bool h2 = (lane & 2) != 0;
    float t0 = h2 ? k2 : k0, t1 = h2 ? k3 : k1;
    float u0 = h2 ? k0 : k2, u1 = h2 ? k1 : k3;
    t0 += __shfl_xor_sync(0xffffffffu, u0, 2);
    t1 += __shfl_xor_sync(0xffffffffu, u1, 2);
    bool h4 = (lane & 4) != 0;
    float v = h4 ? t1 : t0;
    float w = h4 ? t0 : t1;
    v += __shfl_xor_sync(0xffffffffu, w, 4);
    v += __shfl_xor_sync(0xffffffffu, v, 8);
    v += __shfl_xor_sync(0xffffffffu, v, 16);
    return v;
}
__device__ __forceinline__ int bitrev3(int l) {
    return ((l & 1) << 2) | (l & 2) | ((l >> 2) & 1);
}

__global__ void __launch_bounds__(TPB, 4)
pointer_attn_kernel(const float* __restrict__ state_t,
                    const float* __restrict__ context,
                    const int*   __restrict__ mask,
                    const float* __restrict__ Wq,
                    const float* __restrict__ Wk_mha,
                    const float* __restrict__ Wv,
                    const float* __restrict__ Wfc,
                    const float* __restrict__ Wk,
                    const int*   __restrict__ Tptr,
                    float*       __restrict__ out)
{
    __shared__ float sqkT[1024];
    __shared__ float sscr[4096];
    __shared__ float ssc[1024];
    __shared__ float sswl[32];
    __shared__ float ssq[128];
    __shared__ float ssx[128];
    __shared__ float ssxf[128];
    __shared__ float ssz[128];
    __shared__ float sstate[384];
    __shared__ float ssu[1024];
    __shared__ float sred[16];
    __shared__ float sse[4][8][8];   // [warp][row-in-batch][head] e bounce
    __shared__ int   smask[1000];

    const int b = blockIdx.x;
    const int t = threadIdx.x;
    const int w = t >> 5, lane = t & 31;
    const float NEG_INF = __int_as_float(0xff800000u);

    // ---- prologue ----
    for (int i = t; i < NCTX; i += TPB) smask[i] = mask[(size_t)b * NCTX + i];
    for (int i = t; i < 384; i += TPB) sstate[i] = state_t[(size_t)b * 384 + i];
    ssu[t] = NEG_INF;
    ssu[t + 512] = NEG_INF;
    __syncthreads();

    // q[o] = state . Wq[:,o]
    {
        float a0 = 0.f, a1 = 0.f, a2 = 0.f, a3 = 0.f;
        const float* wq = Wq + t;
#pragma unroll 4
        for (int i = 0; i < 384; i += 4) {
            a0 = fmaf(sstate[i],     wq[(size_t)i * HID], a0);
            a1 = fmaf(sstate[i + 1], wq[(size_t)(i + 1) * HID], a1);
            a2 = fmaf(sstate[i + 2], wq[(size_t)(i + 2) * HID], a2);
            a3 = fmaf(sstate[i + 3], wq[(size_t)(i + 3) * HID], a3);
        }
        ssq[t] = (a0 + a1) + (a2 + a3);
    }
    __syncthreads();

    // qkT[d][h] = 0.25 * sum_j Wk_mha[d][16h+j] * q[16h+j]
    {
        int h = t & 7, d0 = t >> 3;
#pragma unroll
        for (int dd = 0; dd < 8; ++dd) {
            int d = d0 + dd * 16;
            float p = 0.f;
#pragma unroll
            for (int j = 0; j < 16; ++j)
                p = fmaf(Wk_mha[d * HID + h * 16 + j], ssq[h * 16 + j], p);
            sqkT[d * 8 + h] = 0.25f * p;
        }
    }
    __syncthreads();

    ull qkp[4][4];
#pragma unroll
    for (int dd = 0; dd < 4; ++dd)
#pragma unroll
        for (int hp = 0; hp < 4; ++hp)
            qkp[dd][hp] = *(const ull*)(sqkT + (lane * 4 + dd) * 8 + hp * 2);
    const int hsel = bitrev3(lane & 7);

    const float* ctxb = context + (size_t)b * NCTX * DCTX;
    const int base = w * RPW;
    const int rowlim = (NCTX - base < RPW) ? (NCTX - base) : RPW;   // 256,256,256,232

    ull acc[NH][2];
#pragma unroll
    for (int hh = 0; hh < NH; ++hh) { acc[hh][0] = 0ull; acc[hh][1] = 0ull; }
    float lrun = 0.f;

    // ---------- pass 1 ----------
    // main region rows [0,224): no guards (rowlim >= 232 for every warp)
#define P1_BATCH(GUARDED)                                                         \
    {                                                                             \
        float4 cv[8];                                                             \
        _Pragma("unroll")                                                         \
        for (int r = 0; r < 8; ++r) {                                             \
            int rr = i0 + r;                                                      \
            int safe = GUARDED ? ((rr < rowlim) ? rr : 0) : rr;                   \
            cv[r] = *(const float4*)(ctxb + (size_t)(base + safe) * DCTX + lane * 4); \
        }                                                                         \
        _Pragma("unroll")                                                         \
        for (int r = 0; r < 8; ++r) {                                             \
            int rr = i0 + r;                                                      \
            ull cc0 = f2pack(cv[r].x, cv[r].x), cc1 = f2pack(cv[r].y, cv[r].y);   \
            ull cc2 = f2pack(cv[r].z, cv[r].z), cc3 = f2pack(cv[r].w, cv[r].w);   \
            ull p01 = 0ull, p23 = 0ull, p45 = 0ull, p67 = 0ull;                   \
            p01 = ffma2(cc0, qkp[0][0], p01); p23 = ffma2(cc0, qkp[0][1], p23);   \
            p45 = ffma2(cc0, qkp[0][2], p45); p67 = ffma2(cc0, qkp[0][3], p67);   \
            p01 = ffma2(cc1, qkp[1][0], p01); p23 = ffma2(cc1, qkp[1][1], p23);   \
            p45 = ffma2(cc1, qkp[1][2], p45); p67 = ffma2(cc1, qkp[1][3], p67);   \
            p01 = ffma2(cc2, qkp[2][0], p01); p23 = ffma2(cc2, qkp[2][1], p23);   \
            p45 = ffma2(cc2, qkp[2][2], p45); p67 = ffma2(cc2, qkp[2][3], p67);   \
            p01 = ffma2(cc3, qkp[3][0], p01); p23 = ffma2(cc3, qkp[3][1], p23);   \
            p45 = ffma2(cc3, qkp[3][2], p45); p67 = ffma2(cc3, qkp[3][3], p67);   \
            float pv[8];                                                          \
            f2unpack(p01, pv[0], pv[1]); f2unpack(p23, pv[2], pv[3]);             \
            f2unpack(p45, pv[4], pv[5]); f2unpack(p67, pv[6], pv[7]);             \
            float compv = split_butterfly8(pv, lane);                             \
            bool dead = GUARDED ? ((rr >= rowlim) ||                              \
                         (smask[base + ((rr < rowlim) ? rr : 0)] != 0))           \
                                : (smask[base + rr] != 0);                        \
            float e = dead ? 0.f : __expf(compv);                                 \
            if (lane < 8) { lrun += e; sse[w][r][hsel] = e; }                     \
        }                                                                         \
        __syncwarp();                                                             \
        _Pragma("unroll")                                                         \
        for (int r = 0; r < 8; ++r) {                                             \
            float4 e03 = *(const float4*)(&sse[w][r][0]);                         \
            float4 e47 = *(const float4*)(&sse[w][r][4]);                         \
            ull c01 = f2pack(cv[r].x, cv[r].y), c23 = f2pack(cv[r].z, cv[r].w);   \
            ull e2;                                                               \
            e2 = f2pack(e03.x, e03.x); acc[0][0] = ffma2(c01, e2, acc[0][0]); acc[0][1] = ffma2(c23, e2, acc[0][1]); \
            e2 = f2pack(e03.y, e03.y); acc[1][0] = ffma2(c01, e2, acc[1][0]); acc[1][1] = ffma2(c23, e2, acc[1][1]); \
            e2 = f2pack(e03.z, e03.z); acc[2][0] = ffma2(c01, e2, acc[2][0]); acc[2][1] = ffma2(c23, e2, acc[2][1]); \
            e2 = f2pack(e03.w, e03.w); acc[3][0] = ffma2(c01, e2, acc[3][0]); acc[3][1] = ffma2(c23, e2, acc[3][1]); \
            e2 = f2pack(e47.x, e47.x); acc[4][0] = ffma2(c01, e2, acc[4][0]); acc[4][1] = ffma2(c23, e2, acc[4][1]); \
            e2 = f2pack(e47.y, e47.y); acc[5][0] = ffma2(c01, e2, acc[5][0]); acc[5][1] = ffma2(c23, e2, acc[5][1]); \
            e2 = f2pack(e47.z, e47.z); acc[6][0] = ffma2(c01, e2, acc[6][0]); acc[6][1] = ffma2(c23, e2, acc[6][1]); \
            e2 = f2pack(e47.w, e47.w); acc[7][0] = ffma2(c01, e2, acc[7][0]); acc[7][1] = ffma2(c23, e2, acc[7][1]); \
        }                                                                         \
        __syncwarp();                                                             \
    }

    for (int i0 = 0; i0 < 224; i0 += 8) P1_BATCH(0)
    for (int i0 = 224; i0 < RPW; i0 += 8) P1_BATCH(1)
#undef P1_BATCH

    // ---- block-reduce c and l across 4 warps ----
    {
        float* scr = sscr + w * 1024;
#pragma unroll
        for (int hh = 0; hh < NH; ++hh) {
            float x0, x1, x2, x3;
            f2unpack(acc[hh][0], x0, x1);
            f2unpack(acc[hh][1], x2, x3);
            *(float4*)(scr + hh * DCTX + lane * 4) = make_float4(x0, x1, x2, x3);
        }
        if (lane < 8) sswl[w * 8 + hsel] = lrun;
    }
    __syncthreads();
#pragma unroll
    for (int jj = 0; jj < 8; ++jj) {
        int idx = t + jj * TPB;
        ssc[idx] = (sscr[idx] + sscr[1024 + idx]) + (sscr[2048 + idx] + sscr[3072 + idx]);
    }
    if (t < 8) sred[8 + t] = (sswl[t] + sswl[8 + t]) + (sswl[16 + t] + sswl[24 + t]);
    __syncthreads();

    // x[o] = (1/l_h) sum_d c[h][d] Wv[d][o]
    {
        int hh = t >> 4;
        const float* c = ssc + hh * DCTX;
        float a0 = 0.f, a1 = 0.f, a2 = 0.f, a3 = 0.f;
#pragma unroll 4
        for (int d = 0; d < DCTX; d += 4) {
            a0 = fmaf(c[d],     Wv[(size_t)d * HID + t], a0);
            a1 = fmaf(c[d + 1], Wv[(size_t)(d + 1) * HID + t], a1);
            a2 = fmaf(c[d + 2], Wv[(size_t)(d + 2) * HID + t], a2);
            a3 = fmaf(c[d + 3], Wv[(size_t)(d + 3) * HID + t], a3);
        }
        ssx[t] = ((a0 + a1) + (a2 + a3)) / sred[8 + hh];
    }
    __syncthreads();
    // xf = x @ Wfc
    {
        float a0 = 0.f, a1 = 0.f, a2 = 0.f, a3 = 0.f;
#pragma unroll 4
        for (int i = 0; i < HID; i += 4) {
            a0 = fmaf(ssx[i],     Wfc[(size_t)i * HID + t], a0);
            a1 = fmaf(ssx[i + 1], Wfc[(size_t)(i + 1) * HID + t], a1);
            a2 = fmaf(ssx[i + 2], Wfc[(size_t)(i + 2) * HID + t], a2);
            a3 = fmaf(ssx[i + 3], Wfc[(size_t)(i + 3) * HID + t], a3);
        }
        ssxf[t] = (a0 + a1) + (a2 + a3);
    }
    __syncthreads();
    // z[d] = (1/sqrt(HID)) sum_o Wk[d][o] xf[o]
    {
        const float* wk = Wk + (size_t)t * HID;
        float a0 = 0.f, a1 = 0.f, a2 = 0.f, a3 = 0.f;
#pragma unroll 4
        for (int o = 0; o < HID; o += 4) {
            a0 = fmaf(wk[o],     ssxf[o], a0);
            a1 = fmaf(wk[o + 1], ssxf[o + 1], a1);
            a2 = fmaf(wk[o + 2], ssxf[o + 2], a2);
            a3 = fmaf(wk[o + 3], ssxf[o + 3], a3);
        }
        ssz[t] = 0.08838834764831845f * ((a0 + a1) + (a2 + a3));
    }
    __syncthreads();

    // ---------- pass 2 ----------
    float4 zv = *(const float4*)(ssz + lane * 4);
    ull z01 = f2pack(zv.x, zv.y), z23 = f2pack(zv.z, zv.w);

#define P2_BATCH(GUARDED)                                                         \
    {                                                                             \
        float dr[8];                                                              \
        _Pragma("unroll")                                                         \
        for (int r = 0; r < 8; ++r) {                                             \
            int rr = i0 + r;                                                      \
            int safe = GUARDED ? ((rr < rowlim) ? rr : 0) : rr;                   \
            float4 cv = *(const float4*)(ctxb + (size_t)(base + safe) * DCTX + lane * 4); \
            ull s2 = ffma2(f2pack(cv.z, cv.w), z23, 0ull);                        \
            s2 = ffma2(f2pack(cv.x, cv.y), z01, s2);                              \
            float a0, a1; f2unpack(s2, a0, a1);                                   \
            dr[r] = a0 + a1;                                                      \
        }                                                                         \
        float ud = split_butterfly8(dr, lane);                                    \
        if (lane < 8) {                                                           \
            int rr = i0 + hsel;                                                   \
            if (!GUARDED || rr < rowlim)                                          \
                ssu[base + rr] = (smask[base + rr] != 0) ? NEG_INF : 5.f * tanhf(ud); \
        }                                                                         \
    }

    for (int i0 = 0; i0 < 224; i0 += 8) P2_BATCH(0)
    for (int i0 = 224; i0 < RPW; i0 += 8) P2_BATCH(1)
#undef P2_BATCH
    __syncthreads();

    // ---- final masked softmax over u[0..999] ----
    float uk[8];
    float m = NEG_INF;
#pragma unroll
    for (int k = 0; k < 8; ++k) {
        int idx = t + k * TPB;
        uk[k] = (idx < NCTX) ? ssu[idx] : NEG_INF;
        m = fmaxf(m, uk[k]);
    }
    m = fmaxf(m, __shfl_xor_sync(0xffffffffu, m, 16));
    m = fmaxf(m, __shfl_xor_sync(0xffffffffu, m, 8));
    m = fmaxf(m, __shfl_xor_sync(0xffffffffu, m, 4));
    m = fmaxf(m, __shfl_xor_sync(0xffffffffu, m, 2));
    m = fmaxf(m, __shfl_xor_sync(0xffffffffu, m, 1));
    if (lane == 0) sred[w] = m;
    __syncthreads();
    float umax = fmaxf(fmaxf(sred[0], sred[1]), fmaxf(sred[2], sred[3]));

    float invT;
    {
        int iv = Tptr[0];
        float Tv = (iv >= 1 && iv <= 1000000) ? (float)iv : __int_as_float(iv);
        if (!(Tv > 0.f)) Tv = 1.f;
        invT = 1.f / Tv;
    }

    float s = 0.f;
#pragma unroll
    for (int k = 0; k < 8; ++k) {
        uk[k] = __expf((uk[k] - umax) * invT);
        s += uk[k];
    }
    s += __shfl_xor_sync(0xffffffffu, s, 16);
    s += __shfl_xor_sync(0xffffffffu, s, 8);
    s += __shfl_xor_sync(0xffffffffu, s, 4);
    s += __shfl_xor_sync(0xffffffffu, s, 2);
    s += __shfl_xor_sync(0xffffffffu, s, 1);
    if (lane == 0) sred[4 + w] = s;
    __syncthreads();
    float inv_sum = 1.f / ((sred[4] + sred[5]) + (sred[6] + sred[7]));

#pragma unroll
    for (int k = 0; k < 8; ++k) {
        int idx = t + k * TPB;
        if (idx < NCTX) out[(size_t)b * NCTX + idx] = uk[k] * inv_sum;
    }
}

extern "C" void kernel_launch(void* const* d_in, const int* in_sizes, int n_in,
                              void* d_out, int out_size)
{
    const float* state_t = (const float*)d_in[0];
    const float* context = (const float*)d_in[1];
    const int*   mask    = (const int*)d_in[2];
    const float* Wq      = (const float*)d_in[3];
    const float* Wk_mha  = (const float*)d_in[4];
    const float* Wv      = (const float*)d_in[5];
    const float* Wfc     = (const float*)d_in[6];
    const float* Wk      = (const float*)d_in[7];
    const int*   Tptr    = (const int*)d_in[8];

    pointer_attn_kernel<<<BATCH, TPB>>>(
        state_t, context, mask, Wq, Wk_mha, Wv, Wfc, Wk, Tptr, (float*)d_out);
}

// round 11
// speedup vs baseline: 1.5205x; 1.0289x over previous
#include <cuda_runtime.h>
#include <cstdint>

#define BATCH 512
#define NCTX  1000
#define DCTX  128
#define NH    8
#define HID   128
#define TPB   128
#define RPW   256   // rows per warp

typedef unsigned long long ull;

__device__ __forceinline__ ull f2pack(float lo, float hi) {
    ull r; asm("mov.b64 %0, {%1,%2};" : "=l"(r) : "f"(lo), "f"(hi)); return r;
}
__device__ __forceinline__ void f2unpack(ull v, float &lo, float &hi) {
    asm("mov.b64 {%0,%1}, %2;" : "=f"(lo), "=f"(hi) : "l"(v));
}
__device__ __forceinline__ ull ffma2(ull a, ull b, ull c) {
    ull d; asm("fma.rn.f32x2 %0, %1, %2, %3;" : "=l"(d) : "l"(a), "l"(b), "l"(c)); return d;
}

__device__ __forceinline__ void cpasync16(uint32_t dst, const void* src, int srcbytes) {
    asm volatile("cp.async.cg.shared.global [%0], [%1], 16, %2;"
                 :: "r"(dst), "l"(src), "r"(srcbytes));
}
__device__ __forceinline__ void cp_commit() { asm volatile("cp.async.commit_group;"); }
template <int NG> __device__ __forceinline__ void cp_wait() {
    asm volatile("cp.async.wait_group %0;" :: "n"(NG));
}

// split-butterfly: p[8] partials/lane -> full 32-lane sum of index bitrev3(lane&7),
// replicated over the 4 lanes sharing lane&7. 9 SHFL.
__device__ __forceinline__ float split_butterfly8(const float* p, int lane) {
    bool h1 = (lane & 1) != 0;
    float k0 = h1 ? p[4] : p[0], k1 = h1 ? p[5] : p[1];
    float k2 = h1 ? p[6] : p[2], k3 = h1 ? p[7] : p[3];
    float s0 = h1 ? p[0] : p[4], s1 = h1 ? p[1] : p[5];
    float s2 = h1 ? p[2] : p[6], s3 = h1 ? p[3] : p[7];
    k0 += __shfl_xor_sync(0xffffffffu, s0, 1);
    k1 += __shfl_xor_sync(0xffffffffu, s1, 1);
    k2 += __shfl_xor_sync(0xffffffffu, s2, 1);
    k3 += __shfl_xor_sync(0xffffffffu, s3, 1);
    bool h2 = (lane & 2) != 0;
    float t0 = h2 ? k2 : k0, t1 = h2 ? k3 : k1;
    float u0 = h2 ? k0 : k2, u1 = h2 ? k1 : k3;
    t0 += __shfl_xor_sync(0xffffffffu, u0, 2);
    t1 += __shfl_xor_sync(0xffffffffu, u1, 2);
    bool h4 = (lane & 4) != 0;
    float v = h4 ? t1 : t0;
    float w = h4 ? t0 : t1;
    v += __shfl_xor_sync(0xffffffffu, w, 4);
    v += __shfl_xor_sync(0xffffffffu, v, 8);
    v += __shfl_xor_sync(0xffffffffu, v, 16);
    return v;
}
__device__ __forceinline__ int bitrev3(int l) {
    return ((l & 1) << 2) | (l & 2) | ((l >> 2) & 1);
}

__global__ void __launch_bounds__(TPB, 4)
pointer_attn_kernel(const float* __restrict__ state_t,
                    const float* __restrict__ context,
                    const int*   __restrict__ mask,
                    const float* __restrict__ Wq,
                    const float* __restrict__ Wk_mha,
                    const float* __restrict__ Wv,
                    const float* __restrict__ Wfc,
                    const float* __restrict__ Wk,
                    const int*   __restrict__ Tptr,
                    float*       __restrict__ out)
{
    __shared__ float sqkT[1024];
    __shared__ float sscr[4096];   // aliased: p1 staging -> reduce scratch -> p2 staging
    __shared__ float ssc[1024];
    __shared__ float sswl[32];
    __shared__ float ssq[128];
    __shared__ float ssx[128];
    __shared__ float ssxf[128];
    __shared__ float ssz[128];
    __shared__ float sstate[384];
    __shared__ float ssu[1024];
    __shared__ float sred[16];
    __shared__ float sse[4][8][8];
    __shared__ int   smask[1000];

    const int b = blockIdx.x;
    const int t = threadIdx.x;
    const int w = t >> 5, lane = t & 31;
    const float NEG_INF = __int_as_float(0xff800000u);

    const float* ctxb = context + (size_t)b * NCTX * DCTX;
    const int base = w * RPW;
    const int rowlim = (NCTX - base < RPW) ? (NCTX - base) : RPW;   // 256,256,256,232

    const uint32_t stg = (uint32_t)__cvta_generic_to_shared(sscr) + w * 4096;  // bytes
    const char* stgr = (const char*)sscr + w * 4096;

    // stage 4 rows starting i0q into buffer buf (per-warp, per-lane self-copy)
#define STAGE(i0q, buf)                                                            \
    {                                                                              \
        _Pragma("unroll")                                                          \
        for (int r = 0; r < 4; ++r) {                                              \
            int rr = (i0q) + r;                                                    \
            int ok = (rr < rowlim) ? 16 : 0;                                       \
            const float* src = ctxb + (size_t)(base + ((rr < rowlim) ? rr : 0)) * DCTX + lane * 4; \
            cpasync16(stg + (buf) * 2048 + r * 512 + lane * 16, src, ok);          \
        }                                                                          \
        cp_commit();                                                               \
    }

    // ---- prologue ----
    for (int i = t; i < NCTX; i += TPB) smask[i] = mask[(size_t)b * NCTX + i];
    for (int i = t; i < 384; i += TPB) sstate[i] = state_t[(size_t)b * 384 + i];
    ssu[t] = NEG_INF;
    ssu[t + 512] = NEG_INF;

    // kick off pass-1 batch 0 prefetch under the q/qk prologue
    STAGE(0, 0)
    __syncthreads();

    // q[o] = state . Wq[:,o]
    {
        float a0 = 0.f, a1 = 0.f, a2 = 0.f, a3 = 0.f;
        const float* wq = Wq + t;
#pragma unroll 4
        for (int i = 0; i < 384; i += 4) {
            a0 = fmaf(sstate[i],     wq[(size_t)i * HID], a0);
            a1 = fmaf(sstate[i + 1], wq[(size_t)(i + 1) * HID], a1);
            a2 = fmaf(sstate[i + 2], wq[(size_t)(i + 2) * HID], a2);
            a3 = fmaf(sstate[i + 3], wq[(size_t)(i + 3) * HID], a3);
        }
        ssq[t] = (a0 + a1) + (a2 + a3);
    }
    __syncthreads();

    // qkT[d][h] = 0.25 * sum_j Wk_mha[d][16h+j] * q[16h+j]
    {
        int h = t & 7, d0 = t >> 3;
#pragma unroll
        for (int dd = 0; dd < 8; ++dd) {
            int d = d0 + dd * 16;
            float p = 0.f;
#pragma unroll
            for (int j = 0; j < 16; ++j)
                p = fmaf(Wk_mha[d * HID + h * 16 + j], ssq[h * 16 + j], p);
            sqkT[d * 8 + h] = 0.25f * p;
        }
    }
    __syncthreads();

    ull qkp[4][4];
#pragma unroll
    for (int dd = 0; dd < 4; ++dd)
#pragma unroll
        for (int hp = 0; hp < 4; ++hp)
            qkp[dd][hp] = *(const ull*)(sqkT + (lane * 4 + dd) * 8 + hp * 2);
    const int hsel = bitrev3(lane & 7);

    ull acc[NH][2];
#pragma unroll
    for (int hh = 0; hh < NH; ++hh) { acc[hh][0] = 0ull; acc[hh][1] = 0ull; }
    float lrun = 0.f;

    // ---------- pass 1 (4-row staged batches, prefetch depth 1) ----------
#define P1_COMPUTE(GUARDED)                                                        \
    {                                                                              \
        const int buf = (i0 >> 2) & 1;                                             \
        float4 cv[4];                                                              \
        _Pragma("unroll")                                                          \
        for (int r = 0; r < 4; ++r)                                                \
            cv[r] = *(const float4*)(stgr + buf * 2048 + r * 512 + lane * 16);     \
        _Pragma("unroll")                                                          \
        for (int r = 0; r < 4; ++r) {                                              \
            int rr = i0 + r;                                                       \
            ull cc0 = f2pack(cv[r].x, cv[r].x), cc1 = f2pack(cv[r].y, cv[r].y);    \
            ull cc2 = f2pack(cv[r].z, cv[r].z), cc3 = f2pack(cv[r].w, cv[r].w);    \
            ull p01 = 0ull, p23 = 0ull, p45 = 0ull, p67 = 0ull;                    \
            p01 = ffma2(cc0, qkp[0][0], p01); p23 = ffma2(cc0, qkp[0][1], p23);    \
            p45 = ffma2(cc0, qkp[0][2], p45); p67 = ffma2(cc0, qkp[0][3], p67);    \
            p01 = ffma2(cc1, qkp[1][0], p01); p23 = ffma2(cc1, qkp[1][1], p23);    \
            p45 = ffma2(cc1, qkp[1][2], p45); p67 = ffma2(cc1, qkp[1][3], p67);    \
            p01 = ffma2(cc2, qkp[2][0], p01); p23 = ffma2(cc2, qkp[2][1], p23);    \
            p45 = ffma2(cc2, qkp[2][2], p45); p67 = ffma2(cc2, qkp[2][3], p67);    \
            p01 = ffma2(cc3, qkp[3][0], p01); p23 = ffma2(cc3, qkp[3][1], p23);    \
            p45 = ffma2(cc3, qkp[3][2], p45); p67 = ffma2(cc3, qkp[3][3], p67);    \
            float pv[8];                                                           \
            f2unpack(p01, pv[0], pv[1]); f2unpack(p23, pv[2], pv[3]);              \
            f2unpack(p45, pv[4], pv[5]); f2unpack(p67, pv[6], pv[7]);              \
            float compv = split_butterfly8(pv, lane);                              \
            bool dead = GUARDED ? ((rr >= rowlim) ||                               \
                         (smask[base + ((rr < rowlim) ? rr : 0)] != 0))            \
                                : (smask[base + rr] != 0);                         \
            float e = dead ? 0.f : __expf(compv);                                  \
            if (lane < 8) { lrun += e; sse[w][r][hsel] = e; }                      \
        }                                                                          \
        __syncwarp();                                                              \
        _Pragma("unroll")                                                          \
        for (int r = 0; r < 4; ++r) {                                              \
            float4 e03 = *(const float4*)(&sse[w][r][0]);                          \
            float4 e47 = *(const float4*)(&sse[w][r][4]);                          \
            ull c01 = f2pack(cv[r].x, cv[r].y), c23 = f2pack(cv[r].z, cv[r].w);    \
            ull e2;                                                                \
            e2 = f2pack(e03.x, e03.x); acc[0][0] = ffma2(c01, e2, acc[0][0]); acc[0][1] = ffma2(c23, e2, acc[0][1]); \
            e2 = f2pack(e03.y, e03.y); acc[1][0] = ffma2(c01, e2, acc[1][0]); acc[1][1] = ffma2(c23, e2, acc[1][1]); \
            e2 = f2pack(e03.z, e03.z); acc[2][0] = ffma2(c01, e2, acc[2][0]); acc[2][1] = ffma2(c23, e2, acc[2][1]); \
            e2 = f2pack(e03.w, e03.w); acc[3][0] = ffma2(c01, e2, acc[3][0]); acc[3][1] = ffma2(c23, e2, acc[3][1]); \
            e2 = f2pack(e47.x, e47.x); acc[4][0] = ffma2(c01, e2, acc[4][0]); acc[4][1] = ffma2(c23, e2, acc[4][1]); \
            e2 = f2pack(e47.y, e47.y); acc[5][0] = ffma2(c01, e2, acc[5][0]); acc[5][1] = ffma2(c23, e2, acc[5][1]); \
            e2 = f2pack(e47.z, e47.z); acc[6][0] = ffma2(c01, e2, acc[6][0]); acc[6][1] = ffma2(c23, e2, acc[6][1]); \
            e2 = f2pack(e47.w, e47.w); acc[7][0] = ffma2(c01, e2, acc[7][0]); acc[7][1] = ffma2(c23, e2, acc[7][1]); \
        }                                                                          \
        __syncwarp();                                                              \
    }

    for (int i0 = 0; i0 < 224; i0 += 4) {
        STAGE(i0 + 4, ((i0 >> 2) & 1) ^ 1)
        cp_wait<1>();
        P1_COMPUTE(0)
    }
    for (int i0 = 224; i0 < RPW; i0 += 4) {
        if (i0 + 4 < RPW) { STAGE(i0 + 4, ((i0 >> 2) & 1) ^ 1) cp_wait<1>(); }
        else              { cp_wait<0>(); }
        P1_COMPUTE(1)
    }
#undef P1_COMPUTE

    // ---- block-reduce c and l across 4 warps (sscr reused as scratch) ----
    {
        float* scr = sscr + w * 1024;
#pragma unroll
        for (int hh = 0; hh < NH; ++hh) {
            float x0, x1, x2, x3;
            f2unpack(acc[hh][0], x0, x1);
            f2unpack(acc[hh][1], x2, x3);
            *(float4*)(scr + hh * DCTX + lane * 4) = make_float4(x0, x1, x2, x3);
        }
        if (lane < 8) sswl[w * 8 + hsel] = lrun;
    }
    __syncthreads();
#pragma unroll
    for (int jj = 0; jj < 8; ++jj) {
        int idx = t + jj * TPB;
        ssc[idx] = (sscr[idx] + sscr[1024 + idx]) + (sscr[2048 + idx] + sscr[3072 + idx]);
    }
    if (t < 8) sred[8 + t] = (sswl[t] + sswl[8 + t]) + (sswl[16 + t] + sswl[24 + t]);
    __syncthreads();

    // sscr free again — kick off pass-2 batch 0 prefetch under the matvecs
    STAGE(0, 0)

    // x[o] = (1/l_h) sum_d c[h][d] Wv[d][o]
    {
        int hh = t >> 4;
        const float* c = ssc + hh * DCTX;
        float a0 = 0.f, a1 = 0.f, a2 = 0.f, a3 = 0.f;
#pragma unroll 4
        for (int d = 0; d < DCTX; d += 4) {
            a0 = fmaf(c[d],     Wv[(size_t)d * HID + t], a0);
            a1 = fmaf(c[d + 1], Wv[(size_t)(d + 1) * HID + t], a1);
            a2 = fmaf(c[d + 2], Wv[(size_t)(d + 2) * HID + t], a2);
            a3 = fmaf(c[d + 3], Wv[(size_t)(d + 3) * HID + t], a3);
        }
        ssx[t] = ((a0 + a1) + (a2 + a3)) / sred[8 + hh];
    }
    __syncthreads();
    // xf = x @ Wfc
    {
        float a0 = 0.f, a1 = 0.f, a2 = 0.f, a3 = 0.f;
#pragma unroll 4
        for (int i = 0; i < HID; i += 4) {
            a0 = fmaf(ssx[i],     Wfc[(size_t)i * HID + t], a0);
            a1 = fmaf(ssx[i + 1], Wfc[(size_t)(i + 1) * HID + t], a1);
            a2 = fmaf(ssx[i + 2], Wfc[(size_t)(i + 2) * HID + t], a2);
            a3 = fmaf(ssx[i + 3], Wfc[(size_t)(i + 3) * HID + t], a3);
        }
        ssxf[t] = (a0 + a1) + (a2 + a3);
    }
    __syncthreads();
    // z[d] = (1/sqrt(HID)) sum_o Wk[d][o] xf[o]
    {
        const float* wk = Wk + (size_t)t * HID;
        float a0 = 0.f, a1 = 0.f, a2 = 0.f, a3 = 0.f;
#pragma unroll 4
        for (int o = 0; o < HID; o += 4) {
            a0 = fmaf(wk[o],     ssxf[o], a0);
            a1 = fmaf(wk[o + 1], ssxf[o + 1], a1);
            a2 = fmaf(wk[o + 2], ssxf[o + 2], a2);
            a3 = fmaf(wk[o + 3], ssxf[o + 3], a3);
        }
        ssz[t] = 0.08838834764831845f * ((a0 + a1) + (a2 + a3));
    }
    __syncthreads();

    // ---------- pass 2 (staged, butterfly per 8 rows = 2 batches) ----------
    float4 zv = *(const float4*)(ssz + lane * 4);
    ull z01 = f2pack(zv.x, zv.y), z23 = f2pack(zv.z, zv.w);

    for (int ib = 0; ib < RPW; ib += 8) {
        float dr[8];
#pragma unroll
        for (int half = 0; half < 2; ++half) {
            int i0 = ib + half * 4;
            int buf = (i0 >> 2) & 1;
            if (i0 + 4 < RPW) { STAGE(i0 + 4, buf ^ 1) cp_wait<1>(); }
            else              { cp_wait<0>(); }
#pragma unroll
            for (int r = 0; r < 4; ++r) {
                float4 cv = *(const float4*)(stgr + buf * 2048 + r * 512 + lane * 16);
                ull s2 = ffma2(f2pack(cv.z, cv.w), z23, 0ull);
                s2 = ffma2(f2pack(cv.x, cv.y), z01, s2);
                float a0, a1; f2unpack(s2, a0, a1);
                dr[half * 4 + r] = a0 + a1;
            }
        }
        float ud = split_butterfly8(dr, lane);
        if (lane < 8) {
            int rr = ib + hsel;
            if (rr < rowlim)
                ssu[base + rr] = (smask[base + rr] != 0) ? NEG_INF : 5.f * tanhf(ud);
        }
    }
#undef STAGE
    __syncthreads();

    // ---- final masked softmax over u[0..999] ----
    float uk[8];
    float m = NEG_INF;
#pragma unroll
    for (int k = 0; k < 8; ++k) {
        int idx = t + k * TPB;
        uk[k] = (idx < NCTX) ? ssu[idx] : NEG_INF;
        m = fmaxf(m, uk[k]);
    }
    m = fmaxf(m, __shfl_xor_sync(0xffffffffu, m, 16));
    m = fmaxf(m, __shfl_xor_sync(0xffffffffu, m, 8));
    m = fmaxf(m, __shfl_xor_sync(0xffffffffu, m, 4));
    m = fmaxf(m, __shfl_xor_sync(0xffffffffu, m, 2));
    m = fmaxf(m, __shfl_xor_sync(0xffffffffu, m, 1));
    if (lane == 0) sred[w] = m;
    __syncthreads();
    float umax = fmaxf(fmaxf(sred[0], sred[1]), fmaxf(sred[2], sred[3]));

    float invT;
    {
        int iv = Tptr[0];
        float Tv = (iv >= 1 && iv <= 1000000) ? (float)iv : __int_as_float(iv);
        if (!(Tv > 0.f)) Tv = 1.f;
        invT = 1.f / Tv;
    }

    float s = 0.f;
#pragma unroll
    for (int k = 0; k < 8; ++k) {
        uk[k] = __expf((uk[k] - umax) * invT);
        s += uk[k];
    }
    s += __shfl_xor_sync(0xffffffffu, s, 16);
    s += __shfl_xor_sync(0xffffffffu, s, 8);
    s += __shfl_xor_sync(0xffffffffu, s, 4);
    s += __shfl_xor_sync(0xffffffffu, s, 2);
    s += __shfl_xor_sync(0xffffffffu, s, 1);
    if (lane == 0) sred[4 + w] = s;
    __syncthreads();
    float inv_sum = 1.f / ((sred[4] + sred[5]) + (sred[6] + sred[7]));

#pragma unroll
    for (int k = 0; k < 8; ++k) {
        int idx = t + k * TPB;
        if (idx < NCTX) out[(size_t)b * NCTX + idx] = uk[k] * inv_sum;
    }
}

extern "C" void kernel_launch(void* const* d_in, const int* in_sizes, int n_in,
                              void* d_out, int out_size)
{
    const float* state_t = (const float*)d_in[0];
    const float* context = (const float*)d_in[1];
    const int*   mask    = (const int*)d_in[2];
    const float* Wq      = (const float*)d_in[3];
    const float* Wk_mha  = (const float*)d_in[4];
    const float* Wv      = (const float*)d_in[5];
    const float* Wfc     = (const float*)d_in[6];
    const float* Wk      = (const float*)d_in[7];
    const int*   Tptr    = (const int*)d_in[8];

    pointer_attn_kernel<<<BATCH, TPB>>>(
        state_t, context, mask, Wq, Wk_mha, Wv, Wfc, Wk, Tptr, (float*)d_out);
}